// round 1
// baseline (speedup 1.0000x reference)
#include <cuda_runtime.h>

// loss = 0.5 * ( sum_j ( (y-mu)^2/sigma + log(sigma) ) + NT*log(2*pi) ) / (NT*BS)
// computed over the LAST row only (reference selects log_prob[-1]).

#define BS 4096
#define NT 2048
#define THREADS 512          // 512 threads * 4 floats = 2048 = NT

__global__ void criterion_last_row_kernel(const float* __restrict__ mu,
                                          const float* __restrict__ sigma,
                                          const float* __restrict__ ty,
                                          float* __restrict__ out) {
    const long long base = (long long)(BS - 1) * NT;
    const int tid = threadIdx.x;

    // Each thread handles 4 contiguous floats via float4.
    const float4 m4 = reinterpret_cast<const float4*>(mu + base)[tid];
    const float4 s4 = reinterpret_cast<const float4*>(sigma + base)[tid];
    const float4 y4 = reinterpret_cast<const float4*>(ty + base)[tid];

    float acc = 0.0f;
    {
        float d;
        d = y4.x - m4.x; acc += d * d / s4.x + __logf(s4.x);
        d = y4.y - m4.y; acc += d * d / s4.y + __logf(s4.y);
        d = y4.z - m4.z; acc += d * d / s4.z + __logf(s4.z);
        d = y4.w - m4.w; acc += d * d / s4.w + __logf(s4.w);
    }

    // warp reduce
    #pragma unroll
    for (int off = 16; off > 0; off >>= 1)
        acc += __shfl_xor_sync(0xFFFFFFFFu, acc, off);

    // cross-warp reduce via shared memory
    __shared__ float warp_sums[THREADS / 32];
    const int wid = tid >> 5;
    const int lid = tid & 31;
    if (lid == 0) warp_sums[wid] = acc;
    __syncthreads();

    if (wid == 0) {
        float v = (lid < THREADS / 32) ? warp_sums[lid] : 0.0f;
        #pragma unroll
        for (int off = 8; off > 0; off >>= 1)
            v += __shfl_xor_sync(0xFFFFFFFFu, v, off);
        if (lid == 0) {
            const float LOG_2PI = 1.8378770664093453f;
            float loss = 0.5f * (v + (float)NT * LOG_2PI) / ((float)NT * (float)BS);
            out[0] = loss;
        }
    }
}

extern "C" void kernel_launch(void* const* d_in, const int* in_sizes, int n_in,
                              void* d_out, int out_size) {
    const float* mu    = (const float*)d_in[0];
    const float* sigma = (const float*)d_in[1];
    const float* ty    = (const float*)d_in[2];
    float* out = (float*)d_out;
    criterion_last_row_kernel<<<1, THREADS>>>(mu, sigma, ty, out);
}